// round 15
// baseline (speedup 1.0000x reference)
#include <cuda_runtime.h>
#include <cuda_bf16.h>
#include <cstdint>

#define N_NODES   100000
#define N_EDGES   1200000
#define NUM_GRAPHS 128
#define IN_DIM    5
#define HIDDEN    64
#define CAP       128          // bucket capacity; P(deg>=128)~1e-60 for Poisson(12)

#define NB_FILL   ((N_EDGES / 4 + 255) / 256)       // 1172
#define NB_XPACK  ((N_NODES * 8) / 256)              // 3125
#define NB_PREP   2

// -------- scratch (device globals; zero at module load; every replay
//          restores the state it found) --------
__device__ __align__(16) float g_h1   [N_NODES * HIDDEN];    // 25.6 MB fp32
__device__ __align__(16) float g_xp   [N_NODES * 8];         // 3.2 MB padded x
__device__ __align__(16) unsigned short g_h1h [N_NODES * HIDDEN];
__device__ __align__(16) unsigned short g_h1l [N_NODES * HIDDEN];
__device__ __align__(16) unsigned short g_aggh[N_NODES * HIDDEN];
__device__ __align__(16) unsigned short g_aggl[N_NODES * HIDDEN];
__device__ __align__(16) unsigned short g_wh_rel [HIDDEN * HIDDEN]; // W_rel2^T hi [n][k]
__device__ __align__(16) unsigned short g_wl_rel [HIDDEN * HIDDEN];
__device__ __align__(16) unsigned short g_wh_root[HIDDEN * HIDDEN];
__device__ __align__(16) unsigned short g_wl_root[HIDDEN * HIDDEN];
__device__ __align__(16) float g_pool [NUM_GRAPHS * HIDDEN];  // zeroed by k_head post-read
__device__              float g_cnt  [NUM_GRAPHS];
__device__ int   g_deg  [N_NODES];                            // zeroed by k_gather post-read
__device__ int   g_slots[N_NODES * CAP];                      // 51.2 MB bucket CSR

static __device__ __forceinline__ void bfsplit(float v, unsigned short& h, unsigned short& l) {
    __nv_bfloat16 bh = __float2bfloat16(v);
    float r = v - __bfloat162float(bh);
    __nv_bfloat16 bl = __float2bfloat16(r);
    h = __bfloat16_as_ushort(bh);
    l = __bfloat16_as_ushort(bl);
}

// -------- K1: fused prep: bucket fill | graph counts | weight splits | x-pack --------
__global__ void k_fill(const int* __restrict__ src, const int* __restrict__ dst,
                       const int* __restrict__ batch,
                       const float* __restrict__ x,
                       const float* __restrict__ w_rel2,
                       const float* __restrict__ w_root2) {
    const int bid = blockIdx.x;
    const int t = threadIdx.x;

    if (bid < NB_FILL) {
        int e4 = bid * 256 + t;
        if (e4 >= N_EDGES / 4) return;
        int4 s = reinterpret_cast<const int4*>(src)[e4];
        int4 d = reinterpret_cast<const int4*>(dst)[e4];
        int p;
        p = atomicAdd(&g_deg[d.x], 1); if (p < CAP) g_slots[d.x * CAP + p] = s.x;
        p = atomicAdd(&g_deg[d.y], 1); if (p < CAP) g_slots[d.y * CAP + p] = s.y;
        p = atomicAdd(&g_deg[d.z], 1); if (p < CAP) g_slots[d.z * CAP + p] = s.z;
        p = atomicAdd(&g_deg[d.w], 1); if (p < CAP) g_slots[d.w * CAP + p] = s.w;
    } else if (bid == NB_FILL) {
        if (t < NUM_GRAPHS) {
            int g = t;
            int lo = 0, hi = N_NODES;
            while (lo < hi) { int mid = (lo + hi) >> 1; if (batch[mid] < g) lo = mid + 1; else hi = mid; }
            int lb0 = lo;
            lo = 0; hi = N_NODES;
            while (lo < hi) { int mid = (lo + hi) >> 1; if (batch[mid] < g + 1) lo = mid + 1; else hi = mid; }
            g_cnt[g] = (float)(lo - lb0);
        }
    } else if (bid == NB_FILL + 1) {
        // transpose + split weights: out[n*64+k] = split(w[k*64+n])
        for (int idx = t; idx < HIDDEN * HIDDEN; idx += 256) {
            int n = idx >> 6, k = idx & 63;
            unsigned short h, l;
            bfsplit(w_rel2[k * 64 + n], h, l);
            g_wh_rel[idx] = h; g_wl_rel[idx] = l;
            bfsplit(w_root2[k * 64 + n], h, l);
            g_wh_root[idx] = h; g_wl_root[idx] = l;
        }
    } else {
        // x-pack: xp[n*8+c] = c<5 ? x[n*5+c] : 0
        int idx = (bid - NB_FILL - NB_PREP) * 256 + t;
        if (idx < N_NODES * 8) {
            int n = idx >> 3, c = idx & 7;
            g_xp[idx] = (c < IN_DIM) ? x[n * IN_DIM + c] : 0.f;
        }
    }
}

// -------- K2: fused layer-1: gather xp[src] + GraphConv; emits fp32 + split --------
__global__ __launch_bounds__(256)
void k_layer1(const float* __restrict__ w_rel,   // [5,64]
              const float* __restrict__ b_rel,
              const float* __restrict__ w_root)  // [5,64]
{
    __shared__ float swr[IN_DIM * HIDDEN];
    __shared__ float swo[IN_DIM * HIDDEN];
    __shared__ float sb[HIDDEN];
    __shared__ float sagg[64][IN_DIM];
    __shared__ float sx  [64][IN_DIM];

    const int t = threadIdx.x;
    const int base = blockIdx.x * 64;

    for (int i = t; i < IN_DIM * HIDDEN; i += 256) { swr[i] = w_rel[i]; swo[i] = w_root[i]; }
    if (t < HIDDEN) sb[t] = b_rel[t];

    {
        const int nl = t >> 2, l = t & 3;
        const int n = base + nl;
        float a0=0,a1=0,a2=0,a3=0,a4=0;
        if (n < N_NODES) {
            int deg = min(g_deg[n], CAP);
            const int* row = g_slots + n * CAP;
            for (int i = l; i < deg; i += 4) {
                const float* sr = g_xp + (size_t)row[i] * 8;
                float4 v0 = *reinterpret_cast<const float4*>(sr);
                float  v4 = sr[4];
                a0 += v0.x; a1 += v0.y; a2 += v0.z; a3 += v0.w; a4 += v4;
            }
        }
        #pragma unroll
        for (int off = 1; off <= 2; off <<= 1) {
            a0 += __shfl_xor_sync(0xFFFFFFFFu, a0, off);
            a1 += __shfl_xor_sync(0xFFFFFFFFu, a1, off);
            a2 += __shfl_xor_sync(0xFFFFFFFFu, a2, off);
            a3 += __shfl_xor_sync(0xFFFFFFFFu, a3, off);
            a4 += __shfl_xor_sync(0xFFFFFFFFu, a4, off);
        }
        if (l == 0 && n < N_NODES) {
            sagg[nl][0]=a0; sagg[nl][1]=a1; sagg[nl][2]=a2; sagg[nl][3]=a3; sagg[nl][4]=a4;
            const float* xr = g_xp + (size_t)n * 8;
            float4 v0 = *reinterpret_cast<const float4*>(xr);
            sx[nl][0]=v0.x; sx[nl][1]=v0.y; sx[nl][2]=v0.z; sx[nl][3]=v0.w; sx[nl][4]=xr[4];
        }
    }
    __syncthreads();

    #pragma unroll 4
    for (int it = 0; it < 16; it++) {
        int idx = it * 256 + t;
        int nl = idx >> 6, j = idx & 63;
        int node = base + nl;
        if (node >= N_NODES) break;
        float acc = sb[j];
        #pragma unroll
        for (int k = 0; k < IN_DIM; k++)
            acc += sagg[nl][k] * swr[k * HIDDEN + j] + sx[nl][k] * swo[k * HIDDEN + j];
        acc = fmaxf(acc, 0.f);
        size_t o = (size_t)node * HIDDEN + j;
        g_h1[o] = acc;
        unsigned short h, l; bfsplit(acc, h, l);
        g_h1h[o] = h;
        g_h1l[o] = l;
    }
}

// -------- K3: neighbor gather: agg[n] = sum h1[src] -> bf16 hi/lo split --------
__global__ __launch_bounds__(256)
void k_gather() {
    const int t = threadIdx.x;
    const int lane = t & 31, wid = t >> 5;
    const int li = lane & 15;
    const int node = blockIdx.x * 16 + wid * 2 + (lane >> 4);   // grid 6250 -> exactly 100000

    int deg = min(g_deg[node], CAP);
    const int* row = g_slots + node * CAP;
    float a0 = 0.f, a1 = 0.f, a2 = 0.f, a3 = 0.f;

    int i = 0;
    for (; i + 4 <= deg; i += 4) {
        int s0 = row[i], s1 = row[i + 1], s2 = row[i + 2], s3 = row[i + 3];
        float4 v0 = *reinterpret_cast<const float4*>(&g_h1[(size_t)s0 * HIDDEN + li * 4]);
        float4 v1 = *reinterpret_cast<const float4*>(&g_h1[(size_t)s1 * HIDDEN + li * 4]);
        float4 v2 = *reinterpret_cast<const float4*>(&g_h1[(size_t)s2 * HIDDEN + li * 4]);
        float4 v3 = *reinterpret_cast<const float4*>(&g_h1[(size_t)s3 * HIDDEN + li * 4]);
        a0 += (v0.x + v1.x) + (v2.x + v3.x);
        a1 += (v0.y + v1.y) + (v2.y + v3.y);
        a2 += (v0.z + v1.z) + (v2.z + v3.z);
        a3 += (v0.w + v1.w) + (v2.w + v3.w);
    }
    for (; i < deg; i++) {
        float4 v = *reinterpret_cast<const float4*>(&g_h1[(size_t)row[i] * HIDDEN + li * 4]);
        a0 += v.x; a1 += v.y; a2 += v.z; a3 += v.w;
    }

    unsigned short h0,l0,h1,l1,h2,l2,h3,l3;
    bfsplit(a0, h0, l0); bfsplit(a1, h1, l1);
    bfsplit(a2, h2, l2); bfsplit(a3, h3, l3);
    size_t o = (size_t)node * HIDDEN + li * 4;
    *(uint2*)&g_aggh[o] = make_uint2((uint32_t)h0 | ((uint32_t)h1 << 16),
                                     (uint32_t)h2 | ((uint32_t)h3 << 16));
    *(uint2*)&g_aggl[o] = make_uint2((uint32_t)l0 | ((uint32_t)l1 << 16),
                                     (uint32_t)l2 | ((uint32_t)l3 << 16));
    if (li == 0) g_deg[node] = 0;        // reset for next replay
}

// ====== K4: layer-2 GEMM TM=128 (mma.sync bf16 split) + cp.async double-buffer ======
#define TM 128
#define SA_ST 72                 // ushort stride: 144B/row -> 4-bank shift/row
#define ARR_A (TM * SA_ST * 2)        // 18432 B
#define ARR_W (HIDDEN * SA_ST * 2)    // 9216 B
#define OA0H 0
#define OA0L (OA0H + ARR_A)
#define OW0H (OA0L + ARR_A)           // 36864
#define OW0L (OW0H + ARR_W)
#define OA1H (OW0L + ARR_W)           // 55296
#define OA1L (OA1H + ARR_A)
#define OW1H (OA1L + ARR_A)           // 92160
#define OW1L (OW1H + ARR_W)
#define OBIAS (OW1L + ARR_W)          // 110592
#define OBATCH (OBIAS + 256)          // 110848
#define SMEM_MM (OBATCH + 512)        // 111360 bytes -> 2 blocks/SM

#define CP_ASYNC16(dst_u32, src_ptr) \
    asm volatile("cp.async.cg.shared.global [%0], [%1], 16;" \
                 :: "r"(dst_u32), "l"(src_ptr) : "memory")
#define CP_COMMIT()  asm volatile("cp.async.commit_group;" ::: "memory")
#define CP_WAIT(n)   asm volatile("cp.async.wait_group %0;" :: "n"(n) : "memory")

static __device__ __forceinline__ uint32_t smem_u32(const void* p) {
    uint32_t a;
    asm("{ .reg .u64 t; cvta.to.shared.u64 t, %1; cvt.u32.u64 %0, t; }" : "=r"(a) : "l"(p));
    return a;
}
static __device__ __forceinline__ void mma16816(float* c, uint32_t a0, uint32_t a1,
                                                uint32_t a2, uint32_t a3,
                                                uint32_t b0, uint32_t b1) {
    asm volatile(
        "mma.sync.aligned.m16n8k16.row.col.f32.bf16.bf16.f32 "
        "{%0,%1,%2,%3}, {%4,%5,%6,%7}, {%8,%9}, {%0,%1,%2,%3};"
        : "+f"(c[0]), "+f"(c[1]), "+f"(c[2]), "+f"(c[3])
        : "r"(a0), "r"(a1), "r"(a2), "r"(a3), "r"(b0), "r"(b1));
}

__global__ void k_layer2mm(const int* __restrict__ batch,
                           const float* __restrict__ b_rel)
{
    extern __shared__ __align__(16) char smem[];
    const uint32_t sb_u32 = smem_u32(smem);
    float* sbias  = (float*)(smem + OBIAS);
    int*   sbatch = (int*)(smem + OBATCH);

    const int t    = threadIdx.x;
    const int lane = t & 31, wid = t >> 5;
    const int base = blockIdx.x * TM;
    const int mmax = min(TM, N_NODES - base);

    if (t < HIDDEN) sbias[t] = b_rel[t];
    if (t < TM) sbatch[t] = (base + t < N_NODES) ? batch[base + t] : -1;

    // ---- zero invalid A rows (last block only) before async copies land ----
    if (mmax < TM) {
        for (int idx = t; idx < (TM - mmax) * 8; idx += 256) {
            int row = mmax + (idx >> 3), c = idx & 7;
            uint32_t o = (uint32_t)(row * (SA_ST * 2) + c * 16);
            *(uint4*)(smem + OA0H + o) = make_uint4(0, 0, 0, 0);
            *(uint4*)(smem + OA0L + o) = make_uint4(0, 0, 0, 0);
            *(uint4*)(smem + OA1H + o) = make_uint4(0, 0, 0, 0);
            *(uint4*)(smem + OA1L + o) = make_uint4(0, 0, 0, 0);
        }
    }

    // ---- stage 0 async: A0 = agg splits (128 rows), W0 = W_rel splits ----
    #pragma unroll
    for (int r = 0; r < 4; r++) {
        int idx = r * 256 + t;                  // 0..1023
        int row = idx >> 3, c = idx & 7;
        uint32_t doff = (uint32_t)(row * (SA_ST * 2) + c * 16);
        if (base + row < N_NODES) {
            CP_ASYNC16(sb_u32 + OA0H + doff, g_aggh + (size_t)(base + row) * HIDDEN + c * 8);
            CP_ASYNC16(sb_u32 + OA0L + doff, g_aggl + (size_t)(base + row) * HIDDEN + c * 8);
        }
    }
    #pragma unroll
    for (int r = 0; r < 2; r++) {
        int idx = r * 256 + t;                  // 0..511
        int row = idx >> 3, c = idx & 7;
        uint32_t doff = (uint32_t)(row * (SA_ST * 2) + c * 16);
        CP_ASYNC16(sb_u32 + OW0H + doff, g_wh_rel + row * HIDDEN + c * 8);
        CP_ASYNC16(sb_u32 + OW0L + doff, g_wl_rel + row * HIDDEN + c * 8);
    }
    CP_COMMIT();

    // ---- stage 1 async: A1 = h1 splits, W1 = W_root splits ----
    #pragma unroll
    for (int r = 0; r < 4; r++) {
        int idx = r * 256 + t;
        int row = idx >> 3, c = idx & 7;
        uint32_t doff = (uint32_t)(row * (SA_ST * 2) + c * 16);
        if (base + row < N_NODES) {
            CP_ASYNC16(sb_u32 + OA1H + doff, g_h1h + (size_t)(base + row) * HIDDEN + c * 8);
            CP_ASYNC16(sb_u32 + OA1L + doff, g_h1l + (size_t)(base + row) * HIDDEN + c * 8);
        }
    }
    #pragma unroll
    for (int r = 0; r < 2; r++) {
        int idx = r * 256 + t;
        int row = idx >> 3, c = idx & 7;
        uint32_t doff = (uint32_t)(row * (SA_ST * 2) + c * 16);
        CP_ASYNC16(sb_u32 + OW1H + doff, g_wh_root + row * HIDDEN + c * 8);
        CP_ASYNC16(sb_u32 + OW1L + doff, g_wl_root + row * HIDDEN + c * 8);
    }
    CP_COMMIT();

    // warp tile: 32 rows x 32 cols (2 m-tiles x 4 n-tiles)
    const int wm = (wid & 3) * 32;
    const int wn = (wid >> 2) * 32;
    const int g  = lane >> 2, tg = lane & 3;

    float acc[2][4][4];
    #pragma unroll
    for (int mt = 0; mt < 2; mt++)
        #pragma unroll
        for (int nt = 0; nt < 4; nt++)
            #pragma unroll
            for (int c = 0; c < 4; c++) acc[mt][nt][c] = 0.f;

    #define GEMM_PRODUCT(SA, SW)                                                       \
        _Pragma("unroll")                                                              \
        for (int ks = 0; ks < 4; ks++) {                                               \
            int kb = ks * 16;                                                          \
            _Pragma("unroll")                                                          \
            for (int mt = 0; mt < 2; mt++) {                                           \
                const unsigned short* ar0 = &(SA)[(wm + mt * 16 + g) * SA_ST + kb + tg * 2]; \
                uint32_t a0 = *(const uint32_t*)ar0;                                   \
                uint32_t a1 = *(const uint32_t*)(ar0 + 8 * SA_ST);                     \
                uint32_t a2 = *(const uint32_t*)(ar0 + 8);                             \
                uint32_t a3 = *(const uint32_t*)(ar0 + 8 * SA_ST + 8);                 \
                _Pragma("unroll")                                                      \
                for (int nt = 0; nt < 4; nt++) {                                       \
                    const unsigned short* br = &(SW)[(wn + nt * 8 + g) * SA_ST + kb + tg * 2]; \
                    uint32_t b0 = *(const uint32_t*)br;                                \
                    uint32_t b1 = *(const uint32_t*)(br + 8);                          \
                    mma16816(acc[mt][nt], a0, a1, a2, a3, b0, b1);                     \
                }                                                                      \
            }                                                                          \
        }

    // wait stage 0 only (stage 1 still in flight), then MMA stage 0
    CP_WAIT(1);
    __syncthreads();
    {
        const unsigned short* sAh = (const unsigned short*)(smem + OA0H);
        const unsigned short* sAl = (const unsigned short*)(smem + OA0L);
        const unsigned short* sWh = (const unsigned short*)(smem + OW0H);
        const unsigned short* sWl = (const unsigned short*)(smem + OW0L);
        GEMM_PRODUCT(sAh, sWh)
        GEMM_PRODUCT(sAh, sWl)
        GEMM_PRODUCT(sAl, sWh)
    }

    // wait stage 1, MMA stage 1
    CP_WAIT(0);
    __syncthreads();
    {
        const unsigned short* sAh = (const unsigned short*)(smem + OA1H);
        const unsigned short* sAl = (const unsigned short*)(smem + OA1L);
        const unsigned short* sWh = (const unsigned short*)(smem + OW1H);
        const unsigned short* sWl = (const unsigned short*)(smem + OW1L);
        GEMM_PRODUCT(sAh, sWh)
        GEMM_PRODUCT(sAh, sWl)
        GEMM_PRODUCT(sAl, sWh)
    }
    __syncthreads();   // before reusing buffer 0 as the f32 C tile

    // ---- bias + relu, stage C [128][64] f32 over A0 region (32 KB <= 36.8 KB) ----
    float* C = (float*)(smem + OA0H);
    #pragma unroll
    for (int mt = 0; mt < 2; mt++) {
        #pragma unroll
        for (int nt = 0; nt < 4; nt++) {
            int col = wn + nt * 8 + tg * 2;
            float2 v0, v1;
            v0.x = fmaxf(acc[mt][nt][0] + sbias[col],     0.f);
            v0.y = fmaxf(acc[mt][nt][1] + sbias[col + 1], 0.f);
            v1.x = fmaxf(acc[mt][nt][2] + sbias[col],     0.f);
            v1.y = fmaxf(acc[mt][nt][3] + sbias[col + 1], 0.f);
            *reinterpret_cast<float2*>(&C[(wm + mt * 16 + g) * 64 + col])     = v0;
            *reinterpret_cast<float2*>(&C[(wm + mt * 16 + g + 8) * 64 + col]) = v1;
        }
    }
    __syncthreads();

    // ---- pooling: sorted batch, run-length flush, 2 row-halves in parallel ----
    if (t < 2 * HIDDEN) {
        int half = t >> 6;           // 0 or 1
        int col = t & 63;
        int r0 = half * 64;
        int r1 = min(r0 + 64, mmax);
        if (r0 < mmax) {
            int gc = sbatch[r0];
            float sum = 0.f;
            for (int m = r0; m < r1; m++) {
                int gg = sbatch[m];
                if (gg != gc) { atomicAdd(&g_pool[gc * HIDDEN + col], sum); gc = gg; sum = 0.f; }
                sum += C[m * 64 + col];
            }
            atomicAdd(&g_pool[gc * HIDDEN + col], sum);
        }
    }
}

// -------- K5: parallel MLP head: block = graph, thread = hidden unit --------
__global__ __launch_bounds__(64)
void k_head(const float* __restrict__ w_h1,  // [128,64]
            const float* __restrict__ b_h1,
            const float* __restrict__ w_h2,  // [64,1]
            const float* __restrict__ b_h2,
            float* __restrict__ out)
{
    __shared__ float s_pool[HIDDEN];
    __shared__ float s_red[2];

    const int g = blockIdx.x;
    const int j = threadIdx.x;

    s_pool[j] = g_pool[g * HIDDEN + j];
    g_pool[g * HIDDEN + j] = 0.f;
    __syncthreads();

    const float inv = 1.f / fmaxf(g_cnt[g], 1.f);

    float acc = b_h1[j];
    #pragma unroll 8
    for (int i = 0; i < HIDDEN; i++) {
        float p = s_pool[i];
        acc += (p * inv) * w_h1[i * HIDDEN + j] + p * w_h1[(HIDDEN + i) * HIDDEN + j];
    }
    float v = fmaxf(acc, 0.f) * w_h2[j];

    #pragma unroll
    for (int off = 16; off > 0; off >>= 1)
        v += __shfl_down_sync(0xFFFFFFFFu, v, off);
    if ((j & 31) == 0) s_red[j >> 5] = v;
    __syncthreads();
    if (j == 0) out[g] = s_red[0] + s_red[1] + b_h2[0];
}

extern "C" void kernel_launch(void* const* d_in, const int* in_sizes, int n_in,
                              void* d_out, int out_size) {
    const float* x       = (const float*)d_in[0];
    const int*   eidx    = (const int*)d_in[1];
    const int*   batch   = (const int*)d_in[2];
    const float* w_rel1  = (const float*)d_in[3];
    const float* b_rel1  = (const float*)d_in[4];
    const float* w_root1 = (const float*)d_in[5];
    const float* w_rel2  = (const float*)d_in[6];
    const float* b_rel2  = (const float*)d_in[7];
    const float* w_root2 = (const float*)d_in[8];
    const float* w_h1    = (const float*)d_in[9];
    const float* b_h1    = (const float*)d_in[10];
    const float* w_h2    = (const float*)d_in[11];
    const float* b_h2    = (const float*)d_in[12];
    float* out = (float*)d_out;

    const int* src = eidx;
    const int* dst = eidx + N_EDGES;

    // not a stream op; legal under graph capture, idempotent
    cudaFuncSetAttribute(k_layer2mm, cudaFuncAttributeMaxDynamicSharedMemorySize, SMEM_MM);

    k_fill    <<<NB_FILL + NB_PREP + NB_XPACK, 256>>>(src, dst, batch, x, w_rel2, w_root2); // 1
    k_layer1  <<<(N_NODES + 63) / 64, 256>>>(w_rel1, b_rel1, w_root1);        // 2
    k_gather  <<<N_NODES / 16, 256>>>();                                       // 3
    k_layer2mm<<<(N_NODES + TM - 1) / TM, 256, SMEM_MM>>>(batch, b_rel2);     // 4 (profiled)
    k_head    <<<NUM_GRAPHS, 64>>>(w_h1, b_h1, w_h2, b_h2, out);              // 5
}

// round 16
// speedup vs baseline: 1.1169x; 1.1169x over previous
#include <cuda_runtime.h>
#include <cuda_bf16.h>
#include <cstdint>

#define N_NODES   100000
#define N_EDGES   1200000
#define NUM_GRAPHS 128
#define IN_DIM    5
#define HIDDEN    64
#define CAP       128          // bucket capacity; P(deg>=128)~1e-60 for Poisson(12)

#define NB_FILL   ((N_EDGES / 4 + 255) / 256)       // 1172
#define NB_XPACK  ((N_NODES * 8) / 256)              // 3125
#define NB_PREP   2

// -------- scratch (device globals; zero at module load; every replay
//          restores the state it found) --------
__device__ __align__(16) float g_xp   [N_NODES * 8];         // 3.2 MB padded x
__device__ __align__(16) unsigned short g_h1h [N_NODES * HIDDEN];  // h1 bf16 hi
__device__ __align__(16) unsigned short g_h1l [N_NODES * HIDDEN];  // h1 bf16 lo
__device__ __align__(16) unsigned short g_aggh[N_NODES * HIDDEN];
__device__ __align__(16) unsigned short g_aggl[N_NODES * HIDDEN];
__device__ __align__(16) unsigned short g_wh_rel [HIDDEN * HIDDEN]; // W_rel2^T hi [n][k]
__device__ __align__(16) unsigned short g_wl_rel [HIDDEN * HIDDEN];
__device__ __align__(16) unsigned short g_wh_root[HIDDEN * HIDDEN];
__device__ __align__(16) unsigned short g_wl_root[HIDDEN * HIDDEN];
__device__ __align__(16) float g_pool [NUM_GRAPHS * HIDDEN];  // zeroed by k_head post-read
__device__              float g_cnt  [NUM_GRAPHS];
__device__ int   g_deg  [N_NODES];                            // zeroed by k_gather post-read
__device__ int   g_slots[N_NODES * CAP];                      // 51.2 MB bucket CSR

static __device__ __forceinline__ void bfsplit(float v, unsigned short& h, unsigned short& l) {
    __nv_bfloat16 bh = __float2bfloat16(v);
    float r = v - __bfloat162float(bh);
    __nv_bfloat16 bl = __float2bfloat16(r);
    h = __bfloat16_as_ushort(bh);
    l = __bfloat16_as_ushort(bl);
}
static __device__ __forceinline__ float bf_lo(uint32_t p) {   // low bf16 of packed pair
    return __uint_as_float(p << 16);
}
static __device__ __forceinline__ float bf_hi(uint32_t p) {   // high bf16 of packed pair
    return __uint_as_float(p & 0xFFFF0000u);
}

// -------- K1: fused prep: bucket fill | graph counts | weight splits | x-pack --------
__global__ void k_fill(const int* __restrict__ src, const int* __restrict__ dst,
                       const int* __restrict__ batch,
                       const float* __restrict__ x,
                       const float* __restrict__ w_rel2,
                       const float* __restrict__ w_root2) {
    const int bid = blockIdx.x;
    const int t = threadIdx.x;

    if (bid < NB_FILL) {
        int e4 = bid * 256 + t;
        if (e4 >= N_EDGES / 4) return;
        int4 s = reinterpret_cast<const int4*>(src)[e4];
        int4 d = reinterpret_cast<const int4*>(dst)[e4];
        int p;
        p = atomicAdd(&g_deg[d.x], 1); if (p < CAP) g_slots[d.x * CAP + p] = s.x;
        p = atomicAdd(&g_deg[d.y], 1); if (p < CAP) g_slots[d.y * CAP + p] = s.y;
        p = atomicAdd(&g_deg[d.z], 1); if (p < CAP) g_slots[d.z * CAP + p] = s.z;
        p = atomicAdd(&g_deg[d.w], 1); if (p < CAP) g_slots[d.w * CAP + p] = s.w;
    } else if (bid == NB_FILL) {
        if (t < NUM_GRAPHS) {
            int g = t;
            int lo = 0, hi = N_NODES;
            while (lo < hi) { int mid = (lo + hi) >> 1; if (batch[mid] < g) lo = mid + 1; else hi = mid; }
            int lb0 = lo;
            lo = 0; hi = N_NODES;
            while (lo < hi) { int mid = (lo + hi) >> 1; if (batch[mid] < g + 1) lo = mid + 1; else hi = mid; }
            g_cnt[g] = (float)(lo - lb0);
        }
    } else if (bid == NB_FILL + 1) {
        // transpose + split weights: out[n*64+k] = split(w[k*64+n])
        for (int idx = t; idx < HIDDEN * HIDDEN; idx += 256) {
            int n = idx >> 6, k = idx & 63;
            unsigned short h, l;
            bfsplit(w_rel2[k * 64 + n], h, l);
            g_wh_rel[idx] = h; g_wl_rel[idx] = l;
            bfsplit(w_root2[k * 64 + n], h, l);
            g_wh_root[idx] = h; g_wl_root[idx] = l;
        }
    } else {
        // x-pack: xp[n*8+c] = c<5 ? x[n*5+c] : 0
        int idx = (bid - NB_FILL - NB_PREP) * 256 + t;
        if (idx < N_NODES * 8) {
            int n = idx >> 3, c = idx & 7;
            g_xp[idx] = (c < IN_DIM) ? x[n * IN_DIM + c] : 0.f;
        }
    }
}

// -------- K2: fused layer-1: gather xp[src] + GraphConv; emits bf16 hi/lo only --------
__global__ __launch_bounds__(256)
void k_layer1(const float* __restrict__ w_rel,   // [5,64]
              const float* __restrict__ b_rel,
              const float* __restrict__ w_root)  // [5,64]
{
    __shared__ float swr[IN_DIM * HIDDEN];
    __shared__ float swo[IN_DIM * HIDDEN];
    __shared__ float sb[HIDDEN];
    __shared__ float sagg[64][IN_DIM];
    __shared__ float sx  [64][IN_DIM];

    const int t = threadIdx.x;
    const int base = blockIdx.x * 64;

    for (int i = t; i < IN_DIM * HIDDEN; i += 256) { swr[i] = w_rel[i]; swo[i] = w_root[i]; }
    if (t < HIDDEN) sb[t] = b_rel[t];

    {
        const int nl = t >> 2, l = t & 3;
        const int n = base + nl;
        float a0=0,a1=0,a2=0,a3=0,a4=0;
        if (n < N_NODES) {
            int deg = min(g_deg[n], CAP);
            const int* row = g_slots + n * CAP;
            for (int i = l; i < deg; i += 4) {
                const float* sr = g_xp + (size_t)row[i] * 8;
                float4 v0 = *reinterpret_cast<const float4*>(sr);
                float  v4 = sr[4];
                a0 += v0.x; a1 += v0.y; a2 += v0.z; a3 += v0.w; a4 += v4;
            }
        }
        #pragma unroll
        for (int off = 1; off <= 2; off <<= 1) {
            a0 += __shfl_xor_sync(0xFFFFFFFFu, a0, off);
            a1 += __shfl_xor_sync(0xFFFFFFFFu, a1, off);
            a2 += __shfl_xor_sync(0xFFFFFFFFu, a2, off);
            a3 += __shfl_xor_sync(0xFFFFFFFFu, a3, off);
            a4 += __shfl_xor_sync(0xFFFFFFFFu, a4, off);
        }
        if (l == 0 && n < N_NODES) {
            sagg[nl][0]=a0; sagg[nl][1]=a1; sagg[nl][2]=a2; sagg[nl][3]=a3; sagg[nl][4]=a4;
            const float* xr = g_xp + (size_t)n * 8;
            float4 v0 = *reinterpret_cast<const float4*>(xr);
            sx[nl][0]=v0.x; sx[nl][1]=v0.y; sx[nl][2]=v0.z; sx[nl][3]=v0.w; sx[nl][4]=xr[4];
        }
    }
    __syncthreads();

    #pragma unroll 4
    for (int it = 0; it < 16; it++) {
        int idx = it * 256 + t;
        int nl = idx >> 6, j = idx & 63;
        int node = base + nl;
        if (node >= N_NODES) break;
        float acc = sb[j];
        #pragma unroll
        for (int k = 0; k < IN_DIM; k++)
            acc += sagg[nl][k] * swr[k * HIDDEN + j] + sx[nl][k] * swo[k * HIDDEN + j];
        acc = fmaxf(acc, 0.f);
        size_t o = (size_t)node * HIDDEN + j;
        unsigned short h, l; bfsplit(acc, h, l);
        g_h1h[o] = h;
        g_h1l[o] = l;
    }
}

// -------- K3: neighbor gather reads bf16-hi h1 (half traffic), fp32 accumulate --------
// 2 nodes per warp; 16 lanes x 4 elements (uint2 of packed bf16 pairs).
__global__ __launch_bounds__(256)
void k_gather() {
    const int t = threadIdx.x;
    const int lane = t & 31, wid = t >> 5;
    const int li = lane & 15;
    const int node = blockIdx.x * 16 + wid * 2 + (lane >> 4);   // grid 6250 -> exactly 100000

    int deg = min(g_deg[node], CAP);
    const int* row = g_slots + node * CAP;
    float a0 = 0.f, a1 = 0.f, a2 = 0.f, a3 = 0.f;

    int i = 0;
    for (; i + 4 <= deg; i += 4) {
        uint2 p0 = *reinterpret_cast<const uint2*>(&g_h1h[(size_t)row[i]     * HIDDEN + li * 4]);
        uint2 p1 = *reinterpret_cast<const uint2*>(&g_h1h[(size_t)row[i + 1] * HIDDEN + li * 4]);
        uint2 p2 = *reinterpret_cast<const uint2*>(&g_h1h[(size_t)row[i + 2] * HIDDEN + li * 4]);
        uint2 p3 = *reinterpret_cast<const uint2*>(&g_h1h[(size_t)row[i + 3] * HIDDEN + li * 4]);
        a0 += (bf_lo(p0.x) + bf_lo(p1.x)) + (bf_lo(p2.x) + bf_lo(p3.x));
        a1 += (bf_hi(p0.x) + bf_hi(p1.x)) + (bf_hi(p2.x) + bf_hi(p3.x));
        a2 += (bf_lo(p0.y) + bf_lo(p1.y)) + (bf_lo(p2.y) + bf_lo(p3.y));
        a3 += (bf_hi(p0.y) + bf_hi(p1.y)) + (bf_hi(p2.y) + bf_hi(p3.y));
    }
    for (; i < deg; i++) {
        uint2 p = *reinterpret_cast<const uint2*>(&g_h1h[(size_t)row[i] * HIDDEN + li * 4]);
        a0 += bf_lo(p.x); a1 += bf_hi(p.x);
        a2 += bf_lo(p.y); a3 += bf_hi(p.y);
    }

    unsigned short h0,l0,h1,l1,h2,l2,h3,l3;
    bfsplit(a0, h0, l0); bfsplit(a1, h1, l1);
    bfsplit(a2, h2, l2); bfsplit(a3, h3, l3);
    size_t o = (size_t)node * HIDDEN + li * 4;
    *(uint2*)&g_aggh[o] = make_uint2((uint32_t)h0 | ((uint32_t)h1 << 16),
                                     (uint32_t)h2 | ((uint32_t)h3 << 16));
    *(uint2*)&g_aggl[o] = make_uint2((uint32_t)l0 | ((uint32_t)l1 << 16),
                                     (uint32_t)l2 | ((uint32_t)l3 << 16));
    if (li == 0) g_deg[node] = 0;        // reset for next replay
}

// ====== K4: layer-2 GEMM (mma.sync bf16 split) with cp.async double-buffer ======
#define TM 64
#define SA_ST 72            // ushort stride: 144B/row -> 4-bank shift/row
#define ARR_B (TM * SA_ST * 2)   // 9216 bytes per array
#define OA0H 0
#define OA0L (OA0H + ARR_B)
#define OW0H (OA0L + ARR_B)
#define OW0L (OW0H + ARR_B)
#define OA1H (OW0L + ARR_B)
#define OA1L (OA1H + ARR_B)
#define OW1H (OA1L + ARR_B)
#define OW1L (OW1H + ARR_B)
#define OBIAS (OW1L + ARR_B)          // 73728
#define OBATCH (OBIAS + 256)
#define SMEM_MM (OBATCH + 256)        // 74240 bytes

#define CP_ASYNC16(dst_u32, src_ptr) \
    asm volatile("cp.async.cg.shared.global [%0], [%1], 16;" \
                 :: "r"(dst_u32), "l"(src_ptr) : "memory")
#define CP_COMMIT()  asm volatile("cp.async.commit_group;" ::: "memory")
#define CP_WAIT(n)   asm volatile("cp.async.wait_group %0;" :: "n"(n) : "memory")

static __device__ __forceinline__ uint32_t smem_u32(const void* p) {
    uint32_t a;
    asm("{ .reg .u64 t; cvta.to.shared.u64 t, %1; cvt.u32.u64 %0, t; }" : "=r"(a) : "l"(p));
    return a;
}
static __device__ __forceinline__ void mma16816(float* c, uint32_t a0, uint32_t a1,
                                                uint32_t a2, uint32_t a3,
                                                uint32_t b0, uint32_t b1) {
    asm volatile(
        "mma.sync.aligned.m16n8k16.row.col.f32.bf16.bf16.f32 "
        "{%0,%1,%2,%3}, {%4,%5,%6,%7}, {%8,%9}, {%0,%1,%2,%3};"
        : "+f"(c[0]), "+f"(c[1]), "+f"(c[2]), "+f"(c[3])
        : "r"(a0), "r"(a1), "r"(a2), "r"(a3), "r"(b0), "r"(b1));
}

__global__ void k_layer2mm(const int* __restrict__ batch,
                           const float* __restrict__ b_rel)
{
    extern __shared__ __align__(16) char smem[];
    const uint32_t sb_u32 = smem_u32(smem);
    float* sbias  = (float*)(smem + OBIAS);
    int*   sbatch = (int*)(smem + OBATCH);

    const int t    = threadIdx.x;
    const int lane = t & 31, wid = t >> 5;
    const int base = blockIdx.x * TM;
    const int mmax = min(TM, N_NODES - base);

    if (t < HIDDEN) sbias[t] = b_rel[t];
    if (t < TM) sbatch[t] = (base + t < N_NODES) ? batch[base + t] : -1;

    // ---- zero invalid A rows (last block only) before async copies land ----
    if (mmax < TM) {
        for (int idx = t; idx < (TM - mmax) * 8; idx += 256) {
            int row = mmax + (idx >> 3), c = idx & 7;
            uint32_t o = (uint32_t)(row * (SA_ST * 2) + c * 16);
            *(uint4*)(smem + OA0H + o) = make_uint4(0, 0, 0, 0);
            *(uint4*)(smem + OA0L + o) = make_uint4(0, 0, 0, 0);
            *(uint4*)(smem + OA1H + o) = make_uint4(0, 0, 0, 0);
            *(uint4*)(smem + OA1L + o) = make_uint4(0, 0, 0, 0);
        }
    }

    // ---- stage 0 async: A0 = agg splits, W0 = W_rel splits ----
    #pragma unroll
    for (int r = 0; r < 8; r++) {
        int idx = r * 256 + t;                 // 0..2047
        int arr = idx >> 9;                    // constant per r-pair
        int row = (idx >> 3) & 63, c = idx & 7;
        uint32_t doff = (uint32_t)(row * (SA_ST * 2) + c * 16);
        if (arr == 0) {
            if (base + row < N_NODES)
                CP_ASYNC16(sb_u32 + OA0H + doff, g_aggh + (size_t)(base + row) * HIDDEN + c * 8);
        } else if (arr == 1) {
            if (base + row < N_NODES)
                CP_ASYNC16(sb_u32 + OA0L + doff, g_aggl + (size_t)(base + row) * HIDDEN + c * 8);
        } else if (arr == 2) {
            CP_ASYNC16(sb_u32 + OW0H + doff, g_wh_rel + row * HIDDEN + c * 8);
        } else {
            CP_ASYNC16(sb_u32 + OW0L + doff, g_wl_rel + row * HIDDEN + c * 8);
        }
    }
    CP_COMMIT();

    // ---- stage 1 async: A1 = h1 splits, W1 = W_root splits ----
    #pragma unroll
    for (int r = 0; r < 8; r++) {
        int idx = r * 256 + t;
        int arr = idx >> 9;
        int row = (idx >> 3) & 63, c = idx & 7;
        uint32_t doff = (uint32_t)(row * (SA_ST * 2) + c * 16);
        if (arr == 0) {
            if (base + row < N_NODES)
                CP_ASYNC16(sb_u32 + OA1H + doff, g_h1h + (size_t)(base + row) * HIDDEN + c * 8);
        } else if (arr == 1) {
            if (base + row < N_NODES)
                CP_ASYNC16(sb_u32 + OA1L + doff, g_h1l + (size_t)(base + row) * HIDDEN + c * 8);
        } else if (arr == 2) {
            CP_ASYNC16(sb_u32 + OW1H + doff, g_wh_root + row * HIDDEN + c * 8);
        } else {
            CP_ASYNC16(sb_u32 + OW1L + doff, g_wl_root + row * HIDDEN + c * 8);
        }
    }
    CP_COMMIT();

    const int wm = (wid & 3) * 16;
    const int wn = (wid >> 2) * 32;
    const int g  = lane >> 2, tg = lane & 3;

    float acc[4][4];
    #pragma unroll
    for (int nt = 0; nt < 4; nt++)
        #pragma unroll
        for (int c = 0; c < 4; c++) acc[nt][c] = 0.f;

    #define GEMM_PRODUCT(SA, SW)                                                   \
        _Pragma("unroll")                                                          \
        for (int ks = 0; ks < 4; ks++) {                                           \
            int kb = ks * 16;                                                      \
            const unsigned short* ar0 = &(SA)[(wm + g) * SA_ST + kb + tg * 2];     \
            uint32_t a0 = *(const uint32_t*)ar0;                                   \
            uint32_t a1 = *(const uint32_t*)(ar0 + 8 * SA_ST);                     \
            uint32_t a2 = *(const uint32_t*)(ar0 + 8);                             \
            uint32_t a3 = *(const uint32_t*)(ar0 + 8 * SA_ST + 8);                 \
            _Pragma("unroll")                                                      \
            for (int nt = 0; nt < 4; nt++) {                                       \
                const unsigned short* br = &(SW)[(wn + nt * 8 + g) * SA_ST + kb + tg * 2]; \
                uint32_t b0 = *(const uint32_t*)br;                                \
                uint32_t b1 = *(const uint32_t*)(br + 8);                          \
                mma16816(acc[nt], a0, a1, a2, a3, b0, b1);                         \
            }                                                                      \
        }

    // wait stage 0 only (stage 1 still in flight), then MMA stage 0
    CP_WAIT(1);
    __syncthreads();
    {
        const unsigned short* sAh = (const unsigned short*)(smem + OA0H);
        const unsigned short* sAl = (const unsigned short*)(smem + OA0L);
        const unsigned short* sWh = (const unsigned short*)(smem + OW0H);
        const unsigned short* sWl = (const unsigned short*)(smem + OW0L);
        GEMM_PRODUCT(sAh, sWh)
        GEMM_PRODUCT(sAh, sWl)
        GEMM_PRODUCT(sAl, sWh)
    }

    // wait stage 1, MMA stage 1
    CP_WAIT(0);
    __syncthreads();
    {
        const unsigned short* sAh = (const unsigned short*)(smem + OA1H);
        const unsigned short* sAl = (const unsigned short*)(smem + OA1L);
        const unsigned short* sWh = (const unsigned short*)(smem + OW1H);
        const unsigned short* sWl = (const unsigned short*)(smem + OW1L);
        GEMM_PRODUCT(sAh, sWh)
        GEMM_PRODUCT(sAh, sWl)
        GEMM_PRODUCT(sAl, sWh)
    }
    __syncthreads();   // before reusing buffer 0 as the f32 C tile

    // ---- bias + relu, stage C [64][64] f32 over buffer-0 region ----
    float* C = (float*)(smem + OA0H);   // 16384 B <= 18432 B
    #pragma unroll
    for (int nt = 0; nt < 4; nt++) {
        int col = wn + nt * 8 + tg * 2;
        float2 v0, v1;
        v0.x = fmaxf(acc[nt][0] + sbias[col],     0.f);
        v0.y = fmaxf(acc[nt][1] + sbias[col + 1], 0.f);
        v1.x = fmaxf(acc[nt][2] + sbias[col],     0.f);
        v1.y = fmaxf(acc[nt][3] + sbias[col + 1], 0.f);
        *reinterpret_cast<float2*>(&C[(wm + g) * 64 + col])     = v0;
        *reinterpret_cast<float2*>(&C[(wm + g + 8) * 64 + col]) = v1;
    }
    __syncthreads();

    // ---- pooling: sorted batch, run-length flush per column ----
    if (t < HIDDEN) {
        int gc = sbatch[0];
        float sum = 0.f;
        for (int m = 0; m < mmax; m++) {
            int gg = sbatch[m];
            if (gg != gc) { atomicAdd(&g_pool[gc * HIDDEN + t], sum); gc = gg; sum = 0.f; }
            sum += C[m * 64 + t];
        }
        atomicAdd(&g_pool[gc * HIDDEN + t], sum);
    }
}

// -------- K5: parallel MLP head: block = graph, thread = hidden unit --------
__global__ __launch_bounds__(64)
void k_head(const float* __restrict__ w_h1,  // [128,64]
            const float* __restrict__ b_h1,
            const float* __restrict__ w_h2,  // [64,1]
            const float* __restrict__ b_h2,
            float* __restrict__ out)
{
    __shared__ float s_pool[HIDDEN];
    __shared__ float s_red[2];

    const int g = blockIdx.x;
    const int j = threadIdx.x;

    s_pool[j] = g_pool[g * HIDDEN + j];
    g_pool[g * HIDDEN + j] = 0.f;
    __syncthreads();

    const float inv = 1.f / fmaxf(g_cnt[g], 1.f);

    float acc = b_h1[j];
    #pragma unroll 8
    for (int i = 0; i < HIDDEN; i++) {
        float p = s_pool[i];
        acc += (p * inv) * w_h1[i * HIDDEN + j] + p * w_h1[(HIDDEN + i) * HIDDEN + j];
    }
    float v = fmaxf(acc, 0.f) * w_h2[j];

    #pragma unroll
    for (int off = 16; off > 0; off >>= 1)
        v += __shfl_down_sync(0xFFFFFFFFu, v, off);
    if ((j & 31) == 0) s_red[j >> 5] = v;
    __syncthreads();
    if (j == 0) out[g] = s_red[0] + s_red[1] + b_h2[0];
}

extern "C" void kernel_launch(void* const* d_in, const int* in_sizes, int n_in,
                              void* d_out, int out_size) {
    const float* x       = (const float*)d_in[0];
    const int*   eidx    = (const int*)d_in[1];
    const int*   batch   = (const int*)d_in[2];
    const float* w_rel1  = (const float*)d_in[3];
    const float* b_rel1  = (const float*)d_in[4];
    const float* w_root1 = (const float*)d_in[5];
    const float* w_rel2  = (const float*)d_in[6];
    const float* b_rel2  = (const float*)d_in[7];
    const float* w_root2 = (const float*)d_in[8];
    const float* w_h1    = (const float*)d_in[9];
    const float* b_h1    = (const float*)d_in[10];
    const float* w_h2    = (const float*)d_in[11];
    const float* b_h2    = (const float*)d_in[12];
    float* out = (float*)d_out;

    const int* src = eidx;
    const int* dst = eidx + N_EDGES;

    // not a stream op; legal under graph capture, idempotent
    cudaFuncSetAttribute(k_layer2mm, cudaFuncAttributeMaxDynamicSharedMemorySize, SMEM_MM);

    k_fill    <<<NB_FILL + NB_PREP + NB_XPACK, 256>>>(src, dst, batch, x, w_rel2, w_root2); // 1
    k_layer1  <<<(N_NODES + 63) / 64, 256>>>(w_rel1, b_rel1, w_root1);        // 2
    k_gather  <<<N_NODES / 16, 256>>>();                                       // 3
    k_layer2mm<<<(N_NODES + TM - 1) / TM, 256, SMEM_MM>>>(batch, b_rel2);     // 4 (profiled)
    k_head    <<<NUM_GRAPHS, 64>>>(w_h1, b_h1, w_h2, b_h2, out);              // 5
}